// round 2
// baseline (speedup 1.0000x reference)
#include <cuda_runtime.h>
#include <cstdint>

#define N_IMG 48
#define H1 512
#define H2 256
#define H3 128
#define NC 20

// Scratch intermediates (channels-last: [n][y][x][ic])
__device__ float g_o1[(size_t)N_IMG * H2 * H2 * NC];   // ~252 MB
__device__ float g_o2[(size_t)N_IMG * H3 * H3 * NC];   // ~63 MB

__device__ __forceinline__ int reflect_idx(int i, int S) {
    // valid for i in [-1, S] with pad width 1, numpy 'reflect' mode
    if (i < 0) return -i;
    if (i >= S) return 2 * S - 2 - i;
    return i;
}

// ---------------------------------------------------------------------------
// Stage 1: reflect-pad-1 + 4x4 stride-2 conv (1 -> 20 ch) + ReLU
// in:  x [48][512][512], w1 [20][1][4][4]
// out: g_o1 [48][256][256][20]
// ---------------------------------------------------------------------------
__global__ __launch_bounds__(256) void stage1_kernel(
    const float* __restrict__ x, const float* __restrict__ w1)
{
    __shared__ __align__(16) float s_x[34 * 34];
    __shared__ __align__(16) float s_w[16 * NC];   // [kykx][oc]

    const int n  = blockIdx.z;
    const int tx = threadIdx.x, ty = threadIdx.y;
    const int tid = ty * 16 + tx;
    const int ox0 = blockIdx.x * 16, oy0 = blockIdx.y * 16;

    // weights: w1[oc][k] -> s_w[k][oc]   (16*NC = 320 elements, strided loop!)
    for (int idx = tid; idx < 16 * NC; idx += 256) {
        int oc = idx / 16, k = idx % 16;
        s_w[k * NC + oc] = w1[idx];
    }

    const float* __restrict__ xin = x + (size_t)n * H1 * H1;
    const int rbase = 2 * oy0 - 1, cbase = 2 * ox0 - 1;
    for (int idx = tid; idx < 34 * 34; idx += 256) {
        int r = idx / 34, c = idx % 34;
        int gr = reflect_idx(rbase + r, H1);
        int gc = reflect_idx(cbase + c, H1);
        s_x[idx] = xin[(size_t)gr * H1 + gc];
    }
    __syncthreads();

    float acc[NC];
#pragma unroll
    for (int oc = 0; oc < NC; oc++) acc[oc] = 0.0f;

#pragma unroll
    for (int ky = 0; ky < 4; ky++) {
#pragma unroll
        for (int kx = 0; kx < 4; kx++) {
            float v = s_x[(2 * ty + ky) * 34 + 2 * tx + kx];
            const float4* wp = (const float4*)(s_w + (ky * 4 + kx) * NC);
#pragma unroll
            for (int j = 0; j < 5; j++) {
                float4 w4 = wp[j];
                acc[4 * j + 0] = fmaf(v, w4.x, acc[4 * j + 0]);
                acc[4 * j + 1] = fmaf(v, w4.y, acc[4 * j + 1]);
                acc[4 * j + 2] = fmaf(v, w4.z, acc[4 * j + 2]);
                acc[4 * j + 3] = fmaf(v, w4.w, acc[4 * j + 3]);
            }
        }
    }

    float* __restrict__ op =
        g_o1 + (((size_t)n * H2 + (oy0 + ty)) * H2 + (ox0 + tx)) * NC;
#pragma unroll
    for (int j = 0; j < 5; j++) {
        float4 v4;
        v4.x = fmaxf(acc[4 * j + 0], 0.0f);
        v4.y = fmaxf(acc[4 * j + 1], 0.0f);
        v4.z = fmaxf(acc[4 * j + 2], 0.0f);
        v4.w = fmaxf(acc[4 * j + 3], 0.0f);
        *(float4*)(op + 4 * j) = v4;
    }
}

// ---------------------------------------------------------------------------
// Stage 2: reflect-pad-1 + 4x4 stride-2 conv (20 -> 20 ch) + ReLU  [dominant]
// in:  g_o1 [48][256][256][20], w2 [20][20][4][4]
// out: g_o2 [48][128][128][20]
// Tile: 16 (x) * 8 (y) outputs per block, 128 threads, 1 output pixel/thread.
// smem: planar input [ic][18][34] + transposed weights [ic][k][oc].
// ---------------------------------------------------------------------------
#define S2_IN_PIX (18 * 34)          // 612 pixels
#define S2_IN_ELEMS (S2_IN_PIX * NC) // 12240 floats
#define S2_W_ELEMS (NC * 16 * NC)    // 6400 floats
#define S2_SMEM_BYTES ((S2_IN_ELEMS + S2_W_ELEMS) * 4)

__global__ __launch_bounds__(128) void stage2_kernel(const float* __restrict__ w2)
{
    extern __shared__ __align__(16) float smem[];
    float* s_in = smem;                 // [ic][row(18)][col(34)]
    float* s_w  = smem + S2_IN_ELEMS;   // [ic][k][oc]

    const int n  = blockIdx.z;
    const int tx = threadIdx.x, ty = threadIdx.y;   // 16 x 8
    const int tid = ty * 16 + tx;
    const int ox0 = blockIdx.x * 16, oy0 = blockIdx.y * 8;

    // weights: w2[oc][ic][k] -> s_w[ic*320 + k*20 + oc]
    for (int idx = tid; idx < S2_W_ELEMS; idx += 128) {
        int oc = idx / 320;
        int r  = idx % 320;
        int ic = r / 16, k = r % 16;
        s_w[ic * 320 + k * NC + oc] = w2[idx];
    }

    // input tile (transpose channels-last global -> planar smem)
    const float* __restrict__ ip = g_o1 + (size_t)n * H2 * H2 * NC;
    const int rbase = 2 * oy0 - 1, cbase = 2 * ox0 - 1;
    for (int idx = tid; idx < S2_IN_ELEMS; idx += 128) {
        int pix = idx / NC;
        int ic  = idx % NC;
        int r = pix / 34, c = pix % 34;
        int gr = reflect_idx(rbase + r, H2);
        int gc = reflect_idx(cbase + c, H2);
        s_in[ic * S2_IN_PIX + pix] = ip[((size_t)gr * H2 + gc) * NC + ic];
    }
    __syncthreads();

    float acc[NC];
#pragma unroll
    for (int oc = 0; oc < NC; oc++) acc[oc] = 0.0f;

#pragma unroll 1
    for (int ic = 0; ic < NC; ic++) {
        const float* vrow = s_in + ic * S2_IN_PIX + (2 * ty) * 34 + 2 * tx;
        const float* wic  = s_w + ic * 320;
#pragma unroll
        for (int ky = 0; ky < 4; ky++) {
#pragma unroll
            for (int kx = 0; kx < 4; kx++) {
                float v = vrow[ky * 34 + kx];
                const float4* wp = (const float4*)(wic + (ky * 4 + kx) * NC);
#pragma unroll
                for (int j = 0; j < 5; j++) {
                    float4 w4 = wp[j];
                    acc[4 * j + 0] = fmaf(v, w4.x, acc[4 * j + 0]);
                    acc[4 * j + 1] = fmaf(v, w4.y, acc[4 * j + 1]);
                    acc[4 * j + 2] = fmaf(v, w4.z, acc[4 * j + 2]);
                    acc[4 * j + 3] = fmaf(v, w4.w, acc[4 * j + 3]);
                }
            }
        }
    }

    float* __restrict__ op =
        g_o2 + (((size_t)n * H3 + (oy0 + ty)) * H3 + (ox0 + tx)) * NC;
#pragma unroll
    for (int j = 0; j < 5; j++) {
        float4 v4;
        v4.x = fmaxf(acc[4 * j + 0], 0.0f);
        v4.y = fmaxf(acc[4 * j + 1], 0.0f);
        v4.z = fmaxf(acc[4 * j + 2], 0.0f);
        v4.w = fmaxf(acc[4 * j + 3], 0.0f);
        *(float4*)(op + 4 * j) = v4;
    }
}

// ---------------------------------------------------------------------------
// Stage 3: 3x3 conv zero-pad-1 (20 -> 1 ch) + ReLU
// in:  g_o2 [48][128][128][20], w3 [1][20][3][3]
// out: out [48][128][128]
// ---------------------------------------------------------------------------
__global__ __launch_bounds__(256) void stage3_kernel(
    const float* __restrict__ w3, float* __restrict__ out)
{
    __shared__ __align__(16) float s_in[18 * 18 * NC];  // [pix][ic]
    __shared__ __align__(16) float s_w[9 * NC];          // [k][ic]

    const int n  = blockIdx.z;
    const int tx = threadIdx.x, ty = threadIdx.y;       // 16 x 16
    const int tid = ty * 16 + tx;
    const int ox0 = blockIdx.x * 16, oy0 = blockIdx.y * 16;

    // weights: w3[ic][k] -> s_w[k][ic]  (180 elements < 256 threads)
    if (tid < 9 * NC) {
        int ic = tid / 9, k = tid % 9;
        s_w[k * NC + ic] = w3[tid];
    }

    const float* __restrict__ ip = g_o2 + (size_t)n * H3 * H3 * NC;
    for (int idx = tid; idx < 18 * 18; idx += 256) {
        int r = idx / 18, c = idx % 18;
        int gr = oy0 - 1 + r, gc = ox0 - 1 + c;
        float4* dst = (float4*)(s_in + idx * NC);
        if (gr >= 0 && gr < H3 && gc >= 0 && gc < H3) {
            const float4* src = (const float4*)(ip + ((size_t)gr * H3 + gc) * NC);
#pragma unroll
            for (int j = 0; j < 5; j++) dst[j] = src[j];
        } else {
            float4 z = make_float4(0.f, 0.f, 0.f, 0.f);
#pragma unroll
            for (int j = 0; j < 5; j++) dst[j] = z;
        }
    }
    __syncthreads();

    float acc = 0.0f;
#pragma unroll
    for (int ky = 0; ky < 3; ky++) {
#pragma unroll
        for (int kx = 0; kx < 3; kx++) {
            const float4* vp = (const float4*)(s_in + ((ty + ky) * 18 + (tx + kx)) * NC);
            const float4* wp = (const float4*)(s_w + (ky * 3 + kx) * NC);
#pragma unroll
            for (int j = 0; j < 5; j++) {
                float4 v = vp[j];
                float4 w = wp[j];
                acc = fmaf(v.x, w.x, acc);
                acc = fmaf(v.y, w.y, acc);
                acc = fmaf(v.z, w.z, acc);
                acc = fmaf(v.w, w.w, acc);
            }
        }
    }

    out[((size_t)n * H3 + (oy0 + ty)) * H3 + (ox0 + tx)] = fmaxf(acc, 0.0f);
}

// ---------------------------------------------------------------------------
extern "C" void kernel_launch(void* const* d_in, const int* in_sizes, int n_in,
                              void* d_out, int out_size)
{
    const float* x  = (const float*)d_in[0];   // [16,3,512,512] -> [48][512][512]
    const float* w1 = (const float*)d_in[1];   // [20,1,4,4]
    const float* w2 = (const float*)d_in[2];   // [20,20,4,4]
    const float* w3 = (const float*)d_in[3];   // [1,20,3,3]
    float* out = (float*)d_out;                // [16,3,128,128]

    // Dynamic smem opt-in for stage 2 (74560 B > 48 KB static limit).
    cudaFuncSetAttribute(stage2_kernel,
                         cudaFuncAttributeMaxDynamicSharedMemorySize,
                         S2_SMEM_BYTES);

    stage1_kernel<<<dim3(16, 16, N_IMG), dim3(16, 16)>>>(x, w1);
    stage2_kernel<<<dim3(8, 16, N_IMG), dim3(16, 8), S2_SMEM_BYTES>>>(w2);
    stage3_kernel<<<dim3(8, 8, N_IMG), dim3(16, 16)>>>(w3, out);
}

// round 5
// speedup vs baseline: 1.0350x; 1.0350x over previous
#include <cuda_runtime.h>
#include <cstdint>

#define N_IMG 48
#define H1 512
#define H2 256
#define H3 128
#define NC 20

// Scratch intermediates (channels-last: [n][y][x][ic])
__device__ float g_o1[(size_t)N_IMG * H2 * H2 * NC];   // ~252 MB
__device__ float g_o2[(size_t)N_IMG * H3 * H3 * NC];   // ~63 MB

__device__ __forceinline__ int reflect_idx(int i, int S) {
    if (i < 0) return -i;
    if (i >= S) return 2 * S - 2 - i;
    return i;
}

// ---- packed f32x2 helpers (Blackwell) -------------------------------------
__device__ __forceinline__ uint64_t bcast2(float v) {
    uint64_t r; asm("mov.b64 %0, {%1, %1};" : "=l"(r) : "f"(v)); return r;
}
__device__ __forceinline__ void ffma2(uint64_t& d, uint64_t a, uint64_t b) {
    asm("fma.rn.f32x2 %0, %1, %2, %0;" : "+l"(d) : "l"(a), "l"(b));
}
__device__ __forceinline__ float2 unpk(uint64_t v) {
    float2 f; asm("mov.b64 {%0, %1}, %2;" : "=f"(f.x), "=f"(f.y) : "l"(v)); return f;
}

// 20 output channels (10 packed pairs) for two pixels sharing one weight fetch.
__device__ __forceinline__ void step20x2(const ulonglong2* __restrict__ w5,
                                         uint64_t v0, uint64_t v1,
                                         uint64_t* a0, uint64_t* a1) {
#pragma unroll
    for (int j = 0; j < 5; j++) {
        ulonglong2 w = w5[j];
        ffma2(a0[2*j],   v0, w.x);
        ffma2(a0[2*j+1], v0, w.y);
        ffma2(a1[2*j],   v1, w.x);
        ffma2(a1[2*j+1], v1, w.y);
    }
}

__device__ __forceinline__ void store20(float* op, const uint64_t* acc) {
#pragma unroll
    for (int j = 0; j < 5; j++) {
        float2 p = unpk(acc[2*j]);
        float2 q = unpk(acc[2*j+1]);
        float4 v4 = make_float4(fmaxf(p.x, 0.f), fmaxf(p.y, 0.f),
                                fmaxf(q.x, 0.f), fmaxf(q.y, 0.f));
        *(float4*)(op + 4*j) = v4;
    }
}

// ---------------------------------------------------------------------------
// Stage 1: reflect-pad-1 + 4x4 stride-2 conv (1 -> 20) + ReLU
// tile 32x16 outputs, 256 threads (16x16), 2 px/thread (cols tx, tx+16)
// input tile: 34 rows x 66 cols
// ---------------------------------------------------------------------------
__global__ __launch_bounds__(256) void stage1_kernel(
    const float* __restrict__ x, const float* __restrict__ w1)
{
    __shared__ __align__(16) float s_x[34 * 66];
    __shared__ __align__(16) float s_w[16 * NC];   // [k][oc]

    const int n  = blockIdx.z;
    const int tx = threadIdx.x, ty = threadIdx.y;   // 16 x 16
    const int tid = ty * 16 + tx;
    const int ox0 = blockIdx.x * 32, oy0 = blockIdx.y * 16;

    for (int idx = tid; idx < 16 * NC; idx += 256) {
        int oc = idx / 16, k = idx % 16;
        s_w[k * NC + oc] = w1[idx];
    }

    const float* __restrict__ xin = x + (size_t)n * H1 * H1;
    const int rbase = 2 * oy0 - 1, cbase = 2 * ox0 - 1;
    for (int idx = tid; idx < 34 * 66; idx += 256) {
        int r = idx / 66, c = idx % 66;
        int gr = reflect_idx(rbase + r, H1);
        int gc = reflect_idx(cbase + c, H1);
        s_x[idx] = xin[(size_t)gr * H1 + gc];
    }
    __syncthreads();

    uint64_t acc0[10], acc1[10];
#pragma unroll
    for (int j = 0; j < 10; j++) { acc0[j] = 0ull; acc1[j] = 0ull; }

    const ulonglong2* wb = (const ulonglong2*)s_w;
#pragma unroll
    for (int ky = 0; ky < 4; ky++) {
        const float* vr = s_x + (2 * ty + ky) * 66 + 2 * tx;
        float2 a0 = *(const float2*)(vr);
        float2 b0 = *(const float2*)(vr + 2);
        float2 a1 = *(const float2*)(vr + 32);
        float2 b1 = *(const float2*)(vr + 34);
        const ulonglong2* wk = wb + ky * 20;
        step20x2(wk,      bcast2(a0.x), bcast2(a1.x), acc0, acc1);
        step20x2(wk + 5,  bcast2(a0.y), bcast2(a1.y), acc0, acc1);
        step20x2(wk + 10, bcast2(b0.x), bcast2(b1.x), acc0, acc1);
        step20x2(wk + 15, bcast2(b0.y), bcast2(b1.y), acc0, acc1);
    }

    float* op = g_o1 + (((size_t)n * H2 + (oy0 + ty)) * H2 + (ox0 + tx)) * NC;
    store20(op, acc0);
    store20(op + 16 * NC, acc1);
}

// ---------------------------------------------------------------------------
// Stage 2: reflect-pad-1 + 4x4 stride-2 conv (20 -> 20) + ReLU  [dominant]
// tile 32x16 outputs, 256 threads, 2 px/thread; ic split into 2 passes of 10
// smem: planar input [10][34][66] + transposed weights [10][k][oc]
// ---------------------------------------------------------------------------
#define S2_PLANE (34 * 66)                // 2244
#define S2_ICH 10
#define S2_IN_F (S2_PLANE * S2_ICH)       // 22440
#define S2_W_F  (S2_ICH * 16 * NC)        // 3200
#define S2_SMEM ((S2_IN_F + S2_W_F) * 4)  // 102560 B

__global__ __launch_bounds__(256, 2) void stage2_kernel(const float* __restrict__ w2)
{
    extern __shared__ __align__(16) float smem[];
    float* s_in = smem;                 // [icl][row 34][col 66]
    float* s_w  = smem + S2_IN_F;       // [icl][k][oc]

    const int n  = blockIdx.z;
    const int tx = threadIdx.x, ty = threadIdx.y;   // 16 x 16
    const int tid = ty * 16 + tx;
    const int ox0 = blockIdx.x * 32, oy0 = blockIdx.y * 16;

    const float* __restrict__ ip = g_o1 + (size_t)n * H2 * H2 * NC;
    const int rbase = 2 * oy0 - 1, cbase = 2 * ox0 - 1;

    uint64_t acc0[10], acc1[10];
#pragma unroll
    for (int j = 0; j < 10; j++) { acc0[j] = 0ull; acc1[j] = 0ull; }

#pragma unroll 1
    for (int pass = 0; pass < 2; pass++) {
        const int icb = pass * S2_ICH;
        if (pass) __syncthreads();

        for (int idx = tid; idx < S2_W_F; idx += 256) {
            int icl = idx / 320, rem = idx % 320;
            int k = rem / NC, oc = rem % NC;
            s_w[icl * 320 + k * NC + oc] = w2[oc * 320 + (icb + icl) * 16 + k];
        }
        for (int idx = tid; idx < S2_IN_F; idx += 256) {
            int pix = idx / S2_ICH, icl = idx % S2_ICH;
            int r = pix / 66, c = pix % 66;
            int gr = reflect_idx(rbase + r, H2);
            int gc = reflect_idx(cbase + c, H2);
            s_in[icl * S2_PLANE + pix] = ip[((size_t)gr * H2 + gc) * NC + icb + icl];
        }
        __syncthreads();

#pragma unroll 1
        for (int icl = 0; icl < S2_ICH; icl++) {
            const float* vbase = s_in + icl * S2_PLANE;
            const ulonglong2* wic = (const ulonglong2*)(s_w + icl * 320);
#pragma unroll
            for (int ky = 0; ky < 4; ky++) {
                const float* vr = vbase + (2 * ty + ky) * 66 + 2 * tx;
                float2 a0 = *(const float2*)(vr);
                float2 b0 = *(const float2*)(vr + 2);
                float2 a1 = *(const float2*)(vr + 32);
                float2 b1 = *(const float2*)(vr + 34);
                const ulonglong2* wk = wic + ky * 20;
                step20x2(wk,      bcast2(a0.x), bcast2(a1.x), acc0, acc1);
                step20x2(wk + 5,  bcast2(a0.y), bcast2(a1.y), acc0, acc1);
                step20x2(wk + 10, bcast2(b0.x), bcast2(b1.x), acc0, acc1);
                step20x2(wk + 15, bcast2(b0.y), bcast2(b1.y), acc0, acc1);
            }
        }
    }

    float* op = g_o2 + (((size_t)n * H3 + (oy0 + ty)) * H3 + (ox0 + tx)) * NC;
    store20(op, acc0);
    store20(op + 16 * NC, acc1);
}

// ---------------------------------------------------------------------------
// Stage 3: 3x3 conv zero-pad-1 (20 -> 1) + ReLU
// tile 32x8 outputs, 128 threads (16x8), 2 adjacent px/thread (f32x2 over px)
// smem: planar [ic][10][36] (ic stride 362), weights duplicated u64
// ---------------------------------------------------------------------------
#define S3_ICSTR 362   // 10*36 + 2 pad

__global__ __launch_bounds__(128) void stage3_kernel(
    const float* __restrict__ w3, float* __restrict__ out)
{
    __shared__ __align__(16) float s_in[NC * S3_ICSTR];   // 7240 fl
    __shared__ __align__(16) uint64_t s_wd[NC * 9];       // (w,w) pairs

    const int n  = blockIdx.z;
    const int tx = threadIdx.x, ty = threadIdx.y;   // 16 x 8
    const int tid = ty * 16 + tx;
    const int ox0 = blockIdx.x * 32, oy0 = blockIdx.y * 8;

    // 180 elements, 128 threads -> strided loop (NOT a single guarded write!)
    for (int idx = tid; idx < NC * 9; idx += 128)
        s_wd[idx] = bcast2(w3[idx]);   // [ic][ky][kx]

    const float* __restrict__ ip = g_o2 + (size_t)n * H3 * H3 * NC;
    for (int idx = tid; idx < 360 * NC; idx += 128) {
        int pix = idx / NC, ic = idx % NC;
        int r = pix / 36, c = pix % 36;
        int gy = oy0 - 1 + r, gc = ox0 - 1 + c;
        float v = 0.f;
        if (gy >= 0 && gy < H3 && gc >= 0 && gc < H3)
            v = ip[((size_t)gy * H3 + gc) * NC + ic];
        s_in[ic * S3_ICSTR + pix] = v;
    }
    __syncthreads();

    uint64_t acc = 0ull;   // pair = outputs (2tx, 2tx+1)
#pragma unroll 4
    for (int ic = 0; ic < NC; ic++) {
        const float* base = s_in + ic * S3_ICSTR;
        const uint64_t* wic = s_wd + ic * 9;
#pragma unroll
        for (int ky = 0; ky < 3; ky++) {
            const float* vr = base + (ty + ky) * 36 + 2 * tx;
            uint64_t vA = *(const uint64_t*)(vr);        // cols +0,+1
            uint64_t vB = *(const uint64_t*)(vr + 2);    // cols +2,+3
            uint64_t vM = (vA >> 32) | (vB << 32);       // cols +1,+2
            ffma2(acc, vA, wic[ky * 3 + 0]);
            ffma2(acc, vM, wic[ky * 3 + 1]);
            ffma2(acc, vB, wic[ky * 3 + 2]);
        }
    }

    float2 f = unpk(acc);
    float2 o = make_float2(fmaxf(f.x, 0.f), fmaxf(f.y, 0.f));
    *(float2*)(out + ((size_t)n * H3 + (oy0 + ty)) * H3 + ox0 + 2 * tx) = o;
}

// ---------------------------------------------------------------------------
extern "C" void kernel_launch(void* const* d_in, const int* in_sizes, int n_in,
                              void* d_out, int out_size)
{
    const float* x  = (const float*)d_in[0];
    const float* w1 = (const float*)d_in[1];
    const float* w2 = (const float*)d_in[2];
    const float* w3 = (const float*)d_in[3];
    float* out = (float*)d_out;

    cudaFuncSetAttribute(stage2_kernel,
                         cudaFuncAttributeMaxDynamicSharedMemorySize, S2_SMEM);

    stage1_kernel<<<dim3(8, 16, N_IMG), dim3(16, 16)>>>(x, w1);
    stage2_kernel<<<dim3(4, 8, N_IMG), dim3(16, 16), S2_SMEM>>>(w2);
    stage3_kernel<<<dim3(4, 16, N_IMG), dim3(16, 8)>>>(w3, out);
}

// round 6
// speedup vs baseline: 1.4539x; 1.4048x over previous
#include <cuda_runtime.h>
#include <cstdint>

#define N_IMG 48
#define H1 512
#define H2 256
#define H3 128
#define NC 20

// Stage-2 output scratch (channels-last: [n][y][x][ic]); o1 is fused away.
__device__ float g_o2[(size_t)N_IMG * H3 * H3 * NC];   // ~63 MB

__device__ __forceinline__ int reflect_idx(int i, int S) {
    // numpy 'reflect': valid for i in [-(S-1), 2S-2]
    if (i < 0) return -i;
    if (i >= S) return 2 * S - 2 - i;
    return i;
}

// ---- packed f32x2 helpers (Blackwell) -------------------------------------
__device__ __forceinline__ uint64_t bcast2(float v) {
    uint64_t r; asm("mov.b64 %0, {%1, %1};" : "=l"(r) : "f"(v)); return r;
}
__device__ __forceinline__ uint64_t pack2(float lo, float hi) {
    uint64_t r; asm("mov.b64 %0, {%1, %2};" : "=l"(r) : "f"(lo), "f"(hi)); return r;
}
__device__ __forceinline__ void ffma2(uint64_t& d, uint64_t a, uint64_t b) {
    asm("fma.rn.f32x2 %0, %1, %2, %0;" : "+l"(d) : "l"(a), "l"(b));
}
__device__ __forceinline__ float2 unpk(uint64_t v) {
    float2 f; asm("mov.b64 {%0, %1}, %2;" : "=f"(f.x), "=f"(f.y) : "l"(v)); return f;
}

// 20 output channels (10 packed pairs) for two pixels sharing one weight fetch.
__device__ __forceinline__ void step20x2(const ulonglong2* __restrict__ w5,
                                         uint64_t v0, uint64_t v1,
                                         uint64_t* a0, uint64_t* a1) {
#pragma unroll
    for (int j = 0; j < 5; j++) {
        ulonglong2 w = w5[j];
        ffma2(a0[2*j],   v0, w.x);
        ffma2(a0[2*j+1], v0, w.y);
        ffma2(a1[2*j],   v1, w.x);
        ffma2(a1[2*j+1], v1, w.y);
    }
}

__device__ __forceinline__ void store20(float* op, const uint64_t* acc) {
#pragma unroll
    for (int j = 0; j < 5; j++) {
        float2 p = unpk(acc[2*j]);
        float2 q = unpk(acc[2*j+1]);
        float4 v4 = make_float4(fmaxf(p.x, 0.f), fmaxf(p.y, 0.f),
                                fmaxf(q.x, 0.f), fmaxf(q.y, 0.f));
        *(float4*)(op + 4*j) = v4;
    }
}

// ---------------------------------------------------------------------------
// Fused stage1+stage2: x -> (conv1+relu, recomputed in smem) -> conv2+relu
// Output tile 32x32 of o2 per CTA, 512 threads (16x32), 2 px/thread.
// 4 passes of 5 o1-channels: produce into smem plane, barrier, consume.
// ---------------------------------------------------------------------------
#define FT_X_STRIDE 136
#define FT_X_FL (134 * FT_X_STRIDE)      // 18224
#define FT_O1_STRIDE 68
#define FT_O1_PLANE (66 * FT_O1_STRIDE)  // 4488
#define FT_O1_FL (5 * FT_O1_PLANE)       // 22440
#define FT_W2_FL (NC * 16 * NC)          // 6400
#define FT_SMEM ((FT_X_FL + FT_O1_FL + FT_W2_FL) * 4)  // 188256 B

__global__ __launch_bounds__(512, 1) void fused12_kernel(
    const float* __restrict__ x, const float* __restrict__ w1,
    const float* __restrict__ w2)
{
    extern __shared__ __align__(16) float dsm[];
    float* s_x  = dsm;                        // [134][136]
    float* s_o1 = dsm + FT_X_FL;              // [5][66][68]
    float* s_w2 = dsm + FT_X_FL + FT_O1_FL;   // [ic][k][oc]
    __shared__ __align__(16) uint64_t s_w1A[4][16];  // (oc 5p+0, 5p+1)
    __shared__ __align__(16) uint64_t s_w1B[4][16];  // (oc 5p+2, 5p+3)
    __shared__ float s_w1C[4][16];                   //  oc 5p+4

    const int n  = blockIdx.z;
    const int tx = threadIdx.x, ty = threadIdx.y;    // 16 x 32
    const int tid = ty * 16 + tx;
    const int ox0 = blockIdx.x * 32, oy0 = blockIdx.y * 32;
    const int rbase = 2 * oy0 - 1, cbase = 2 * ox0 - 1;   // o1-space tile origin
    const int xr0 = 4 * oy0 - 3,  xc0 = 4 * ox0 - 3;      // x-space tile origin

    // w2[oc][ic][k] -> s_w2[ic*320 + k*20 + oc]
    for (int idx = tid; idx < FT_W2_FL; idx += 512) {
        int oc = idx / 320, rem = idx % 320;
        int ic = rem / 16, k = rem % 16;
        s_w2[ic * 320 + k * NC + oc] = w2[idx];
    }
    // w1[oc][k] -> packed per-pass taps
    if (tid < 64) {
        int p = tid / 16, k = tid % 16;
        float a = w1[(5*p + 0) * 16 + k];
        float b = w1[(5*p + 1) * 16 + k];
        float c = w1[(5*p + 2) * 16 + k];
        float d = w1[(5*p + 3) * 16 + k];
        s_w1A[p][k] = pack2(a, b);
        s_w1B[p][k] = pack2(c, d);
        s_w1C[p][k] = w1[(5*p + 4) * 16 + k];
    }
    // x tile with x-space reflect
    const float* __restrict__ xin = x + (size_t)n * H1 * H1;
    for (int i = tid; i < 134 * 134; i += 512) {
        int r = i / 134, c = i % 134;
        int gr = reflect_idx(xr0 + r, H1);
        int gc = reflect_idx(xc0 + c, H1);
        s_x[r * FT_X_STRIDE + c] = xin[(size_t)gr * H1 + gc];
    }
    __syncthreads();

    uint64_t acc0[10], acc1[10];
#pragma unroll
    for (int j = 0; j < 10; j++) { acc0[j] = 0ull; acc1[j] = 0ull; }

#pragma unroll 1
    for (int p = 0; p < 4; p++) {
        if (p) __syncthreads();   // previous consume done before overwrite

        // ---- produce: o1 channels [5p, 5p+5) over 66x66 slots -------------
        for (int i = tid; i < 66 * 66; i += 512) {
            int r = i / 66, c = i % 66;
            // slot holds o1[reflect(rbase+r)][reflect(cbase+c)]
            int pr = 2 * (reflect_idx(rbase + r, H2) - rbase);
            int pc = 2 * (reflect_idx(cbase + c, H2) - cbase);
            uint64_t a01 = 0ull, a23 = 0ull; float a4 = 0.f;
#pragma unroll
            for (int ky = 0; ky < 4; ky++) {
                const float* xr = s_x + (pr + ky) * FT_X_STRIDE + pc;
                float2 A = *(const float2*)xr;
                float2 B = *(const float2*)(xr + 2);
                float v[4] = {A.x, A.y, B.x, B.y};
#pragma unroll
                for (int kx = 0; kx < 4; kx++) {
                    int k = ky * 4 + kx;
                    uint64_t vb = bcast2(v[kx]);
                    ffma2(a01, vb, s_w1A[p][k]);
                    ffma2(a23, vb, s_w1B[p][k]);
                    a4 = fmaf(v[kx], s_w1C[p][k], a4);
                }
            }
            float2 f01 = unpk(a01), f23 = unpk(a23);
            float* dst = s_o1 + r * FT_O1_STRIDE + c;
            dst[0 * FT_O1_PLANE] = fmaxf(f01.x, 0.f);
            dst[1 * FT_O1_PLANE] = fmaxf(f01.y, 0.f);
            dst[2 * FT_O1_PLANE] = fmaxf(f23.x, 0.f);
            dst[3 * FT_O1_PLANE] = fmaxf(f23.y, 0.f);
            dst[4 * FT_O1_PLANE] = fmaxf(a4, 0.f);
        }
        __syncthreads();

        // ---- consume: stage2 over ic = 5p+icl -----------------------------
#pragma unroll 1
        for (int icl = 0; icl < 5; icl++) {
            const float* vbase = s_o1 + icl * FT_O1_PLANE;
            const ulonglong2* wic =
                (const ulonglong2*)(s_w2 + (5*p + icl) * 320);
#pragma unroll
            for (int ky = 0; ky < 4; ky++) {
                const float* vr = vbase + (2 * ty + ky) * FT_O1_STRIDE + 2 * tx;
                float2 a0v = *(const float2*)(vr);
                float2 b0v = *(const float2*)(vr + 2);
                float2 a1v = *(const float2*)(vr + 32);
                float2 b1v = *(const float2*)(vr + 34);
                const ulonglong2* wk = wic + ky * 20;
                step20x2(wk,      bcast2(a0v.x), bcast2(a1v.x), acc0, acc1);
                step20x2(wk + 5,  bcast2(a0v.y), bcast2(a1v.y), acc0, acc1);
                step20x2(wk + 10, bcast2(b0v.x), bcast2(b1v.x), acc0, acc1);
                step20x2(wk + 15, bcast2(b0v.y), bcast2(b1v.y), acc0, acc1);
            }
        }
    }

    float* op = g_o2 + (((size_t)n * H3 + (oy0 + ty)) * H3 + (ox0 + tx)) * NC;
    store20(op, acc0);
    store20(op + 16 * NC, acc1);
}

// ---------------------------------------------------------------------------
// Stage 3: 3x3 conv zero-pad-1 (20 -> 1) + ReLU   (unchanged from R5, passed)
// ---------------------------------------------------------------------------
#define S3_ICSTR 362

__global__ __launch_bounds__(128) void stage3_kernel(
    const float* __restrict__ w3, float* __restrict__ out)
{
    __shared__ __align__(16) float s_in[NC * S3_ICSTR];
    __shared__ __align__(16) uint64_t s_wd[NC * 9];

    const int n  = blockIdx.z;
    const int tx = threadIdx.x, ty = threadIdx.y;   // 16 x 8
    const int tid = ty * 16 + tx;
    const int ox0 = blockIdx.x * 32, oy0 = blockIdx.y * 8;

    for (int idx = tid; idx < NC * 9; idx += 128)
        s_wd[idx] = bcast2(w3[idx]);

    const float* __restrict__ ip = g_o2 + (size_t)n * H3 * H3 * NC;
    for (int idx = tid; idx < 360 * NC; idx += 128) {
        int pix = idx / NC, ic = idx % NC;
        int r = pix / 36, c = pix % 36;
        int gy = oy0 - 1 + r, gc = ox0 - 1 + c;
        float v = 0.f;
        if (gy >= 0 && gy < H3 && gc >= 0 && gc < H3)
            v = ip[((size_t)gy * H3 + gc) * NC + ic];
        s_in[ic * S3_ICSTR + pix] = v;
    }
    __syncthreads();

    uint64_t acc = 0ull;
#pragma unroll 4
    for (int ic = 0; ic < NC; ic++) {
        const float* base = s_in + ic * S3_ICSTR;
        const uint64_t* wic = s_wd + ic * 9;
#pragma unroll
        for (int ky = 0; ky < 3; ky++) {
            const float* vr = base + (ty + ky) * 36 + 2 * tx;
            uint64_t vA = *(const uint64_t*)(vr);
            uint64_t vB = *(const uint64_t*)(vr + 2);
            uint64_t vM = (vA >> 32) | (vB << 32);
            ffma2(acc, vA, wic[ky * 3 + 0]);
            ffma2(acc, vM, wic[ky * 3 + 1]);
            ffma2(acc, vB, wic[ky * 3 + 2]);
        }
    }

    float2 f = unpk(acc);
    float2 o = make_float2(fmaxf(f.x, 0.f), fmaxf(f.y, 0.f));
    *(float2*)(out + ((size_t)n * H3 + (oy0 + ty)) * H3 + ox0 + 2 * tx) = o;
}

// ---------------------------------------------------------------------------
extern "C" void kernel_launch(void* const* d_in, const int* in_sizes, int n_in,
                              void* d_out, int out_size)
{
    const float* x  = (const float*)d_in[0];
    const float* w1 = (const float*)d_in[1];
    const float* w2 = (const float*)d_in[2];
    const float* w3 = (const float*)d_in[3];
    float* out = (float*)d_out;

    cudaFuncSetAttribute(fused12_kernel,
                         cudaFuncAttributeMaxDynamicSharedMemorySize, FT_SMEM);

    fused12_kernel<<<dim3(4, 4, N_IMG), dim3(16, 32), FT_SMEM>>>(x, w1, w2);
    stage3_kernel<<<dim3(4, 16, N_IMG), dim3(16, 8)>>>(w3, out);
}